// round 4
// baseline (speedup 1.0000x reference)
#include <cuda_runtime.h>
#include <cuda_bf16.h>
#include <math.h>
#include <stdint.h>

// BornCollapseSampler: logits GEMM + log_softmax + top-k(50) + top-p(0.95)
// + probs + JAX-threefry categorical sampling.
//
// Output layout (float32, tuple flatten order):
//   [0, BSV)            logits
//   [BSV, 2*BSV)        log_probs
//   [2*BSV, 2*BSV+512)  tokens (as float)
//   [2*BSV+512, ...)    probs

#define BDIM 512        // B*S
#define VDIM 50257
#define KDIM 1024
#define TOPK 50
#define TOPP 0.95f

// JAX threefry counter scheme:
//   1 = partitionable (default in recent JAX): per-element uint64 counter i,
//       x = (i>>32, i&0xffffffff), 32-bit output = out0 ^ out1   <-- R3 fix
//   0 = legacy split-iota: counts=iota(N), halves, concat(out0, out1)
#define THREEFRY_PARTITIONABLE 1

static const long long BSV = (long long)BDIM * VDIM;

// ---------------------------------------------------------------------------
// threefry2x32 with key (0, 42)  [jax.random.key(42)]
// ---------------------------------------------------------------------------
__device__ __forceinline__ uint32_t rotl32(uint32_t x, int r) {
    return (x << r) | (x >> (32 - r));
}

__device__ __forceinline__ uint2 tf2x32(uint32_t x0, uint32_t x1) {
    const uint32_t k0 = 0u, k1 = 42u;
    const uint32_t k2 = k0 ^ k1 ^ 0x1BD11BDAu;
    x0 += k0; x1 += k1;
#define TFR(r) { x0 += x1; x1 = rotl32(x1, r); x1 ^= x0; }
    TFR(13) TFR(15) TFR(26) TFR(6)   x0 += k1; x1 += k2 + 1u;
    TFR(17) TFR(29) TFR(16) TFR(24)  x0 += k2; x1 += k0 + 2u;
    TFR(13) TFR(15) TFR(26) TFR(6)   x0 += k0; x1 += k1 + 3u;
    TFR(17) TFR(29) TFR(16) TFR(24)  x0 += k1; x1 += k2 + 4u;
    TFR(13) TFR(15) TFR(26) TFR(6)   x0 += k2; x1 += k0 + 5u;
#undef TFR
    return make_uint2(x0, x1);
}

// gumbel(key(42), (64,8,50257))[flat index i]
__device__ __forceinline__ float gumbel_at(unsigned long long i) {
    uint32_t bits;
#if THREEFRY_PARTITIONABLE
    // counter = uint64 iota; x = (i>>32, i); 32-bit output = out0 ^ out1
    uint2 o = tf2x32((uint32_t)(i >> 32), (uint32_t)i);
    bits = o.x ^ o.y;
#else
    // legacy: counts = iota(N); split halves; out = concat(o0, o1)
    const unsigned long long HALF = ((unsigned long long)BDIM * VDIM) / 2ull; // even
    if (i < HALF) { uint2 o = tf2x32((uint32_t)i, (uint32_t)(i + HALF)); bits = o.x; }
    else          { uint2 o = tf2x32((uint32_t)(i - HALF), (uint32_t)i); bits = o.y; }
#endif
    // uniform in [tiny, 1): f = bitcast((bits>>9)|0x3f800000) - 1; u = max(f, tiny)
    float f = __uint_as_float((bits >> 9) | 0x3f800000u) - 1.0f;
    float u = fmaxf(f, 1.1754943508222875e-38f);
    return -logf(-logf(u));
}

// ---------------------------------------------------------------------------
// GEMM: C[512][50257] = A[512][2048] * B[50257][2048]^T + bias
// A row m: [psi_real(m,:), psi_imag(m,:)];  B row n: [W_real(n,:), W_imag(n,:)]
// Classic fp32 SGEMM, BM=128 BN=128 BK=16, 256 threads, 8x8 microtile.
// ---------------------------------------------------------------------------
#define GBM 128
#define GBN 128
#define GBK 16

__global__ void __launch_bounds__(256)
gemm_kernel(const float* __restrict__ Pr, const float* __restrict__ Pi,
            const float* __restrict__ Wr, const float* __restrict__ Wi,
            const float* __restrict__ bias, float* __restrict__ C)
{
    __shared__ float As[GBK][GBM];
    __shared__ float Bs[GBK][GBN];

    const int tid = threadIdx.x;            // 256
    const int block_n = blockIdx.x * GBN;
    const int block_m = blockIdx.y * GBM;   // M=512 divides evenly
    const int tx = tid & 15;                // 0..15, N direction
    const int ty = tid >> 4;                // 0..15, M direction

    float acc[8][8];
#pragma unroll
    for (int i = 0; i < 8; i++)
#pragma unroll
        for (int j = 0; j < 8; j++) acc[i][j] = 0.0f;

    for (int k0 = 0; k0 < 2 * KDIM; k0 += GBK) {
        const bool real_part = (k0 < KDIM);
        const float* Aptr = real_part ? Pr : Pi;
        const float* Bptr = real_part ? Wr : Wi;
        const int ka = real_part ? k0 : (k0 - KDIM);

        // load A tile (128 rows x 16 k), transpose into As[k][m]
#pragma unroll
        for (int it = 0; it < 2; it++) {
            int s = tid + it * 256;          // 0..511 float4 slots
            int row = s >> 2, kv = s & 3;
            float4 v = *(const float4*)(Aptr + (size_t)(block_m + row) * KDIM + ka + kv * 4);
            As[kv * 4 + 0][row] = v.x;
            As[kv * 4 + 1][row] = v.y;
            As[kv * 4 + 2][row] = v.z;
            As[kv * 4 + 3][row] = v.w;
        }
        // load B tile (128 n-rows x 16 k), transpose into Bs[k][n]
#pragma unroll
        for (int it = 0; it < 2; it++) {
            int s = tid + it * 256;
            int row = s >> 2, kv = s & 3;
            int n = block_n + row;
            float4 v = make_float4(0.f, 0.f, 0.f, 0.f);
            if (n < VDIM)
                v = *(const float4*)(Bptr + (size_t)n * KDIM + ka + kv * 4);
            Bs[kv * 4 + 0][row] = v.x;
            Bs[kv * 4 + 1][row] = v.y;
            Bs[kv * 4 + 2][row] = v.z;
            Bs[kv * 4 + 3][row] = v.w;
        }
        __syncthreads();

#pragma unroll
        for (int kk = 0; kk < GBK; kk++) {
            float4 a0 = *(const float4*)&As[kk][ty * 8];
            float4 a1 = *(const float4*)&As[kk][ty * 8 + 4];
            float4 b0 = *(const float4*)&Bs[kk][tx * 8];
            float4 b1 = *(const float4*)&Bs[kk][tx * 8 + 4];
            float a[8] = {a0.x, a0.y, a0.z, a0.w, a1.x, a1.y, a1.z, a1.w};
            float b[8] = {b0.x, b0.y, b0.z, b0.w, b1.x, b1.y, b1.z, b1.w};
#pragma unroll
            for (int i = 0; i < 8; i++)
#pragma unroll
                for (int j = 0; j < 8; j++)
                    acc[i][j] = fmaf(a[i], b[j], acc[i][j]);
        }
        __syncthreads();
    }

    // epilogue: add bias, store (guard N)
#pragma unroll
    for (int i = 0; i < 8; i++) {
        int m = block_m + ty * 8 + i;
#pragma unroll
        for (int j = 0; j < 8; j++) {
            int n = block_n + tx * 8 + j;
            if (n < VDIM)
                C[(size_t)m * VDIM + n] = acc[i][j] + bias[n];
        }
    }
}

// ---------------------------------------------------------------------------
// Per-row logsumexp
// ---------------------------------------------------------------------------
__device__ float g_lse[BDIM];

__global__ void rowstats_kernel(const float* __restrict__ logits)
{
    const int row = blockIdx.x;
    const float* x = logits + (size_t)row * VDIM;
    __shared__ float red[256];
    const int tid = threadIdx.x;

    float m = -INFINITY;
    for (int i = tid; i < VDIM; i += 256) m = fmaxf(m, x[i]);
    red[tid] = m; __syncthreads();
    for (int s = 128; s > 0; s >>= 1) {
        if (tid < s) red[tid] = fmaxf(red[tid], red[tid + s]);
        __syncthreads();
    }
    m = red[0]; __syncthreads();

    float sum = 0.0f;
    for (int i = tid; i < VDIM; i += 256) sum += expf(x[i] - m);
    red[tid] = sum; __syncthreads();
    for (int s = 128; s > 0; s >>= 1) {
        if (tid < s) red[tid] += red[tid + s];
        __syncthreads();
    }
    if (tid == 0) g_lse[row] = m + logf(red[0]);
}

// ---------------------------------------------------------------------------
// Elementwise: log_probs = logits - lse[row];  probs = 0 (pre-scatter)
// ---------------------------------------------------------------------------
__global__ void postrow_kernel(const float* __restrict__ logits,
                               float* __restrict__ logp,
                               float* __restrict__ probs)
{
    const int row = blockIdx.y;
    const float lse = g_lse[row];
    const size_t base = (size_t)row * VDIM;
    for (int i = blockIdx.x * blockDim.x + threadIdx.x; i < VDIM;
         i += gridDim.x * blockDim.x) {
        logp[base + i]  = logits[base + i] - lse;
        probs[base + i] = 0.0f;
    }
}

// ---------------------------------------------------------------------------
// Per-row: exact rank-50 threshold via 3-round histogram refinement on
// order-preserving keys, then serial top-p + probs scatter + gumbel argmax.
// ---------------------------------------------------------------------------
__device__ __forceinline__ uint32_t float_key(float f) {
    uint32_t u = __float_as_uint(f);
    return (u & 0x80000000u) ? ~u : (u | 0x80000000u);
}

#define CAND_CAP 160

__global__ void toprow_kernel(const float* __restrict__ logits,
                              float* __restrict__ probs,
                              float* __restrict__ tokens)
{
    const int row = blockIdx.x;
    const float* x = logits + (size_t)row * VDIM;
    const int tid = threadIdx.x;   // 256 threads

    __shared__ uint32_t hist[2048];
    __shared__ uint32_t s_prefix;
    __shared__ uint32_t s_rank;
    __shared__ float    cval[CAND_CAP];
    __shared__ uint32_t cidx[CAND_CAP];
    __shared__ uint32_t ccnt;

    uint32_t prefix = 0;
    uint32_t remaining = TOPK;

    // rounds: bits [31:21], [20:10], [9:0]
    for (int round = 0; round < 3; round++) {
        const int shift = (round == 0) ? 21 : (round == 1) ? 10 : 0;
        const int bins  = (round == 2) ? 1024 : 2048;

        for (int i = tid; i < bins; i += 256) hist[i] = 0;
        __syncthreads();

        for (int i = tid; i < VDIM; i += 256) {
            uint32_t key = float_key(x[i]);
            bool ok = (round == 0) ? true
                    : (round == 1) ? ((key >> 21) == prefix)
                                   : ((key >> 10) == prefix);
            if (ok) atomicAdd(&hist[(key >> shift) & (bins - 1)], 1u);
        }
        __syncthreads();

        if (tid == 0) {
            uint32_t cum = 0;
            int b = bins - 1;
            for (; b >= 0; b--) {
                cum += hist[b];
                if (cum >= remaining) break;
            }
            s_prefix = (prefix << ((round == 2) ? 10 : 11)) | (uint32_t)b;
            s_rank   = remaining - (cum - hist[b]);
        }
        __syncthreads();
        prefix    = s_prefix;
        remaining = s_rank;
        __syncthreads();
    }
    const uint32_t thr_key = prefix;  // key of rank-50 element

    // collect candidates: key >= thr_key  (ties at threshold kept, matches ref)
    if (tid == 0) ccnt = 0;
    __syncthreads();
    for (int i = tid; i < VDIM; i += 256) {
        float v = x[i];
        if (float_key(v) >= thr_key) {
            uint32_t p = atomicAdd(&ccnt, 1u);
            if (p < CAND_CAP) { cval[p] = v; cidx[p] = (uint32_t)i; }
        }
    }
    __syncthreads();

    if (tid == 0) {
        int n = (int)min(ccnt, (uint32_t)CAND_CAP);
        // stable sort: value desc, index asc (matches argsort(-logits))
        for (int i = 1; i < n; i++) {
            float v = cval[i]; uint32_t id = cidx[i];
            int j = i - 1;
            while (j >= 0 && (cval[j] < v || (cval[j] == v && cidx[j] > id))) {
                cval[j + 1] = cval[j]; cidx[j + 1] = cidx[j]; j--;
            }
            cval[j + 1] = v; cidx[j + 1] = id;
        }

        float* ework = (float*)hist;   // reuse smem
        const float v0 = cval[0];
        float denom = 0.0f;
        for (int i = 0; i < n; i++) {
            float e = expf(cval[i] - v0);
            ework[i] = e;
            denom += e;
        }
        // top-p: drop i (i>=1) iff cum_before >= p ; kept set is a prefix
        int nkeep = n;
        float cum = 0.0f;
        for (int i = 0; i < n; i++) {
            if (i > 0 && cum >= TOPP) { nkeep = i; break; }
            cum += ework[i] / denom;
        }
        // probs = softmax over kept
        float denom2 = 0.0f;
        for (int i = 0; i < nkeep; i++) denom2 += ework[i];
        for (int i = 0; i < nkeep; i++)
            probs[(size_t)row * VDIM + cidx[i]] = ework[i] / denom2;

        // token = argmax over kept of (logit + gumbel); first-index tie-break
        float best = -INFINITY;
        uint32_t bidx = 0xFFFFFFFFu;
        for (int i = 0; i < nkeep; i++) {
            float g = gumbel_at((unsigned long long)row * VDIM + cidx[i]);
            float s = cval[i] + g;
            if (s > best || (s == best && cidx[i] < bidx)) { best = s; bidx = cidx[i]; }
        }
        tokens[row] = (float)bidx;
    }
}

// ---------------------------------------------------------------------------
// Launch
// ---------------------------------------------------------------------------
extern "C" void kernel_launch(void* const* d_in, const int* in_sizes, int n_in,
                              void* d_out, int out_size)
{
    const float* Pr   = (const float*)d_in[0];   // (64,8,1024)
    const float* Pi   = (const float*)d_in[1];   // (64,8,1024)
    const float* Wr   = (const float*)d_in[2];   // (50257,1024)
    const float* Wi   = (const float*)d_in[3];   // (50257,1024)
    const float* bias = (const float*)d_in[4];   // (50257,)

    float* out    = (float*)d_out;
    float* logits = out;
    float* logp   = out + BSV;
    float* tokens = out + 2 * BSV;
    float* probs  = out + 2 * BSV + BDIM;

    dim3 ggrid((VDIM + GBN - 1) / GBN, BDIM / GBM);   // (393, 4)
    gemm_kernel<<<ggrid, 256>>>(Pr, Pi, Wr, Wi, bias, logits);

    rowstats_kernel<<<BDIM, 256>>>(logits);

    dim3 pgrid(64, BDIM);
    postrow_kernel<<<pgrid, 256>>>(logits, logp, probs);

    toprow_kernel<<<BDIM, 256>>>(logits, probs, tokens);
}